// round 11
// baseline (speedup 1.0000x reference)
#include <cuda_runtime.h>
#include <cstdint>

#define EPS 1e-3f
#define Bn   8
#define CIN  4
#define T0   20
#define S0   24
#define CMID 12
#define T1   18
#define S1   22
#define COUT 36
#define T2   16
#define S2   20
#define HP   24              // padded w-stride of g_h (16B-aligned rows)

#define H_TOTAL (Bn*CMID*T1*S1*S1*HP)

typedef unsigned long long u64;

__device__ float g_h[H_TOTAL];
__device__ float g_stats[24];
__device__ float g_scale[CMID];
__device__ float g_badj[COUT];
__device__ u64   g_Wp[CMID * 18 * 9 * 12];   // pre-scaled packed W2 per ci

__device__ __forceinline__ void ffma2(u64& d, u64 a, u64 b, u64 c) {
    asm("fma.rn.f32x2 %0, %1, %2, %3;" : "=l"(d) : "l"(a), "l"(b), "l"(c));
}
__device__ __forceinline__ u64 pack2(float a, float b) {
    u64 r; asm("mov.b64 %0, {%1, %2};" : "=l"(r) : "f"(a), "f"(b)); return r;
}
__device__ __forceinline__ float lo32(u64 v){ return __uint_as_float((unsigned)v); }
__device__ __forceinline__ float hi32(u64 v){ return __uint_as_float((unsigned)(v>>32)); }

__device__ __forceinline__ void cpa16(uint32_t s, const void* g){
    asm volatile("cp.async.ca.shared.global [%0], [%1], 16;" :: "r"(s), "l"(g));
}
#define CP_COMMIT asm volatile("cp.async.commit_group;")
#define CP_WAIT0  asm volatile("cp.async.wait_group 0;" ::: "memory")

extern __shared__ char smemraw[];

// ---------------------------------------------------------------------------
__global__ void zero_stats_k() {
    if (threadIdx.x < 24) g_stats[threadIdx.x] = 0.0f;
}

// ---------------------------------------------------------------------------
// conv1 + ReLU + stats.  Block = (b, 2 t-planes, d) pair of 22x22 planes.
// 512 thr = 2 ch-groups (6ch = 3 pairs) x 2 t-planes x 128 lanes (121 act).
__global__ void __launch_bounds__(512, 1) conv1_k(const float* __restrict__ x,
                                                  const float* __restrict__ Wg1,
                                                  const float* __restrict__ b1) {
    float2* A0 = (float2*)smemraw;                 // 12 x 24 x 12 f2 = 3456
    float2* A1 = A0 + 3456;
    u64*    Wb0 = (u64*)(A1 + 3456);               // 6p x 9s x 12 = 648
    u64*    Wb1 = Wb0 + 648;
    __shared__ float sred[24];

    const int d  = blockIdx.x;
    const int t0 = 2 * blockIdx.y;
    const int b  = blockIdx.z;
    const int tid = threadIdx.x;
    const int cg  = tid >> 8;
    const int half = tid & 255;
    const int tp  = half >> 7;
    const int pid = half & 127;
    const bool act = pid < 121;
    const int ry = pid / 11;
    const int tx = pid - ry * 11;

    const uint32_t sA0 = (uint32_t)__cvta_generic_to_shared(A0);
    const uint32_t sA1 = (uint32_t)__cvta_generic_to_shared(A1);

    if (tid < 24) sred[tid] = 0.0f;

    auto stageA = [&](uint32_t sbuf, int ci){
#pragma unroll
        for (int k = 0; k < 4; k++) {
            const int i = tid + k * 512;
            if (i < 1728) {
                const int su = i / 144, rem = i - 144*su;
                const int rr = rem / 6, q = rem - 6*rr;
                const int kt4 = su / 3, kd = su - 3*kt4;
                const float* src = x + ((b*CIN + ci)*T0 + (t0+kt4))*(S0*S0*S0)
                                     + (d + kd)*(S0*S0) + rr*S0 + 4*q;
                cpa16(sbuf + (uint32_t)((su*288 + rr*12 + 2*q)*8), src);
            }
        }
    };
    auto stageW = [&](u64* wbuf, int ci){
        const int i = tid;
        if (i < 486) {
            const int p = i / 81, r = i - 81*p;
            const int s = r / 9, t9 = r - 9*s;
            const int kh = t9 / 3, kw = t9 - 3*kh;
            const float w0 = Wg1[(2*p*CIN + ci)*81 + r];
            const float w1 = Wg1[((2*p+1)*CIN + ci)*81 + r];
            wbuf[((p*9 + s)*3 + kh)*4 + kw] = pack2(w0, w1);
        }
    };

    stageA(sA0, 0); CP_COMMIT;
    stageW(Wb0, 0);
    CP_WAIT0;
    __syncthreads();

    u64 acc[3][2][2];
#pragma unroll
    for (int p = 0; p < 3; p++)
#pragma unroll
        for (int r = 0; r < 2; r++) { acc[p][r][0] = 0ull; acc[p][r][1] = 0ull; }

    for (int ci = 0; ci < CIN; ci++) {
        const float2* Ac = (ci & 1) ? A1 : A0;
        const u64*    Wc = (ci & 1) ? Wb1 : Wb0;
        if (ci < CIN-1) {
            stageA((ci & 1) ? sA0 : sA1, ci+1); CP_COMMIT;
            stageW((ci & 1) ? Wb0 : Wb1, ci+1);
        }
        if (act) {
            for (int s9 = 0; s9 < 9; s9++) {
                const int su = s9 + 3*tp;
                u64 xx[4][4];
#pragma unroll
                for (int kr = 0; kr < 4; kr++) {
                    const float2* rp = &Ac[su*288 + (2*ry + kr)*12 + tx];
                    const float2 f0 = rp[0], f1 = rp[1];
                    xx[kr][0] = pack2(f0.x, f0.x);
                    xx[kr][1] = pack2(f0.y, f0.y);
                    xx[kr][2] = pack2(f1.x, f1.x);
                    xx[kr][3] = pack2(f1.y, f1.y);
                }
#pragma unroll
                for (int kh = 0; kh < 3; kh++)
#pragma unroll
                    for (int p = 0; p < 3; p++) {
                        const u64* wb = Wc + ((cg*3 + p)*9 + s9)*12 + kh*4;
                        const ulonglong2 wab = *(const ulonglong2*)wb;
                        const u64 w2v = wb[2];
#pragma unroll
                        for (int r = 0; r < 2; r++)
#pragma unroll
                            for (int c = 0; c < 2; c++) {
                                ffma2(acc[p][r][c], wab.x, xx[r+kh][c+0], acc[p][r][c]);
                                ffma2(acc[p][r][c], wab.y, xx[r+kh][c+1], acc[p][r][c]);
                                ffma2(acc[p][r][c], w2v,   xx[r+kh][c+2], acc[p][r][c]);
                            }
                    }
            }
        }
        CP_WAIT0;
        __syncthreads();
    }

    float ss[3][2] = {{0,0},{0,0},{0,0}}, qq[3][2] = {{0,0},{0,0},{0,0}};
    const int t = t0 + tp;
    if (act) {
#pragma unroll
        for (int p = 0; p < 3; p++) {
            const int j0 = 2*(cg*3 + p);
            const float bj0 = __ldg(&b1[j0]), bj1 = __ldg(&b1[j0+1]);
#pragma unroll
            for (int r = 0; r < 2; r++) {
                const float v00 = fmaxf(lo32(acc[p][r][0]) + bj0, 0.0f);
                const float v01 = fmaxf(lo32(acc[p][r][1]) + bj0, 0.0f);
                const float v10 = fmaxf(hi32(acc[p][r][0]) + bj1, 0.0f);
                const float v11 = fmaxf(hi32(acc[p][r][1]) + bj1, 0.0f);
                const int hb = ((((b*CMID + j0)*T1 + t)*S1 + d)*S1 + (2*ry+r))*HP + 2*tx;
                *(float2*)&g_h[hb] = make_float2(v00, v01);
                *(float2*)&g_h[hb + T1*S1*S1*HP] = make_float2(v10, v11);
                ss[p][0] += v00 + v01;  qq[p][0] += v00*v00 + v01*v01;
                ss[p][1] += v10 + v11;  qq[p][1] += v10*v10 + v11*v11;
            }
        }
    }
    const int lane = tid & 31;
#pragma unroll
    for (int p = 0; p < 3; p++)
#pragma unroll
        for (int hlf = 0; hlf < 2; hlf++) {
            float s_ = ss[p][hlf], q_ = qq[p][hlf];
#pragma unroll
            for (int o = 16; o > 0; o >>= 1) {
                s_ += __shfl_down_sync(0xffffffffu, s_, o);
                q_ += __shfl_down_sync(0xffffffffu, q_, o);
            }
            if (lane == 0) {
                const int j = 2*(cg*3 + p) + hlf;
                atomicAdd(&sred[j], s_);
                atomicAdd(&sred[12 + j], q_);
            }
        }
    __syncthreads();
    if (tid < 24) atomicAdd(&g_stats[tid], sred[tid]);
}

// ---------------------------------------------------------------------------
// finalize + bias adjust (block 0 publishes g_scale).
__global__ void badj_k(const float* __restrict__ W2,
                       const float* __restrict__ b2,
                       const float* __restrict__ gamma,
                       const float* __restrict__ beta) {
    const int j = blockIdx.x;
    const int lane = threadIdx.x;
    __shared__ float ssh[CMID];
    if (lane < CMID) {
        const float N = (float)(Bn * T1 * S1 * S1 * S1);
        const float mean = g_stats[lane] / N;
        const float var  = g_stats[12 + lane] / N - mean * mean;
        const float inv  = rsqrtf(var + EPS);
        const float sc   = gamma[lane] * inv;
        ssh[lane] = beta[lane] - mean * sc;
        if (j == 0) g_scale[lane] = sc;
    }
    __syncwarp();
    float sum = 0.0f;
    for (int e = lane; e < CMID*81; e += 32) {
        const int ci = e / 81;
        sum += W2[j*CMID*81 + e] * ssh[ci];
    }
#pragma unroll
    for (int o = 16; o > 0; o >>= 1) sum += __shfl_down_sync(0xffffffffu, sum, o);
    if (lane == 0) g_badj[j] = b2[j] + sum;
}

// ---------------------------------------------------------------------------
// Pre-scale + pack W2 into g_Wp: [ci][p18][s9][kh*4 + kw] u64 pairs.
__global__ void prepW_k(const float* __restrict__ W2) {
    const int ci = blockIdx.x;              // 0..11
    const float sc = g_scale[ci];
    for (int i = threadIdx.x; i < 18*81; i += blockDim.x) {
        const int p = i / 81, r = i - 81*p;
        const int s = r / 9, t9 = r - 9*s;
        const int kh = t9 / 3, kw = t9 - 3*kh;
        const float w0 = W2[(2*p*CMID + ci)*81 + r] * sc;
        const float w1 = W2[((2*p+1)*CMID + ci)*81 + r] * sc;
        g_Wp[((ci*18 + p)*9 + s)*12 + kh*4 + kw] = pack2(w0, w1);
    }
}

// ---------------------------------------------------------------------------
// conv2 + ReLU.  Block = (b,t,d) 20x20 plane, all 36 ch.  320 thr: 6
// ch-groups (6ch = 3 pairs) x 50 tiles (2r x 4c).  Row-streaming (1 input
// row live), pre-packed weights via cp.async, 2 blocks/SM.
__global__ void __launch_bounds__(320, 2) conv2_k(float* __restrict__ out) {
    float2* A0 = (float2*)smemraw;                 // 9 x 22 x 12 f2 = 2376
    float2* A1 = A0 + 2376;
    u64*    Wb0 = (u64*)(A1 + 2376);               // 18p x 9s x 12 = 1944
    u64*    Wb1 = Wb0 + 1944;

    const int d = blockIdx.x, t = blockIdx.y, b = blockIdx.z;
    const int tid = threadIdx.x;
    const bool act = tid < 300;
    const int cg  = tid / 50;              // 0..5
    const int pid = tid - cg * 50;
    const int ry = pid / 5;                // rows 2ry,2ry+1
    const int tx = pid - ry * 5;           // cols 4tx..4tx+3

    const uint32_t sA0 = (uint32_t)__cvta_generic_to_shared(A0);
    const uint32_t sA1 = (uint32_t)__cvta_generic_to_shared(A1);
    const uint32_t sW0 = (uint32_t)__cvta_generic_to_shared(Wb0);
    const uint32_t sW1 = (uint32_t)__cvta_generic_to_shared(Wb1);

    auto stageA = [&](uint32_t sbuf, int ci){
#pragma unroll
        for (int k = 0; k < 4; k++) {
            const int i = tid + k * 320;
            if (i < 1188) {
                const int su = i / 132, rem = i - 132*su;
                const int rr = rem / 6, q = rem - 6*rr;
                const int kt = su / 3, kd = su - 3*kt;
                const float* src = g_h + ((((b*CMID + ci)*T1 + (t+kt))*S1
                                   + (d + kd))*S1 + rr)*HP + 4*q;
                cpa16(sbuf + (uint32_t)((su*264 + rr*12 + 2*q)*8), src);
            }
        }
    };
    auto stageW = [&](uint32_t sbuf, int ci){
        const u64* src = g_Wp + ci * 1944;
#pragma unroll
        for (int k = 0; k < 4; k++) {
            const int i = tid + k * 320;
            if (i < 972) cpa16(sbuf + (uint32_t)(i*16), src + 2*i);
        }
    };

    stageA(sA0, 0);
    stageW(sW0, 0);
    CP_COMMIT;
    CP_WAIT0;
    __syncthreads();

    u64 acc[3][2][4];
#pragma unroll
    for (int p = 0; p < 3; p++)
#pragma unroll
        for (int r = 0; r < 2; r++)
#pragma unroll
            for (int c = 0; c < 4; c++) acc[p][r][c] = 0ull;

    for (int ci = 0; ci < CMID; ci++) {
        const float2* Ac = (ci & 1) ? A1 : A0;
        const u64*    Wc = (ci & 1) ? Wb1 : Wb0;
        if (ci < CMID-1) {
            stageA((ci & 1) ? sA0 : sA1, ci+1);
            stageW((ci & 1) ? sW0 : sW1, ci+1);
            CP_COMMIT;
        }
        if (act) {
            for (int s9 = 0; s9 < 9; s9++) {
                const u64* wbase = Wc + (cg*3)*9*12 + s9*12;
#pragma unroll
                for (int kr = 0; kr < 4; kr++) {
                    // load input row kr (6 floats), packed as {v,v}
                    const float* rp = (const float*)&Ac[s9*264 + (2*ry + kr)*12 + 2*tx];
                    const float4 v4 = *(const float4*)rp;
                    const float2 v2 = *(const float2*)(rp + 4);
                    u64 xx[6];
                    xx[0] = pack2(v4.x, v4.x);
                    xx[1] = pack2(v4.y, v4.y);
                    xx[2] = pack2(v4.z, v4.z);
                    xx[3] = pack2(v4.w, v4.w);
                    xx[4] = pack2(v2.x, v2.x);
                    xx[5] = pack2(v2.y, v2.y);
#pragma unroll
                    for (int r = 0; r < 2; r++) {
                        const int kh = kr - r;
                        if (kh < 0 || kh > 2) continue;
#pragma unroll
                        for (int p = 0; p < 3; p++) {
                            const u64* wb = wbase + p*108 + kh*4;
                            const ulonglong2 wab = *(const ulonglong2*)wb;
                            const u64 w2v = wb[2];
#pragma unroll
                            for (int c = 0; c < 4; c++) {
                                ffma2(acc[p][r][c], wab.x, xx[c+0], acc[p][r][c]);
                                ffma2(acc[p][r][c], wab.y, xx[c+1], acc[p][r][c]);
                                ffma2(acc[p][r][c], w2v,   xx[c+2], acc[p][r][c]);
                            }
                        }
                    }
                }
            }
        }
        CP_WAIT0;
        __syncthreads();
    }

    if (act) {
#pragma unroll
        for (int p = 0; p < 3; p++) {
            const int j0 = 2*(cg*3 + p);
            const float bj0 = __ldg(&g_badj[j0]), bj1 = __ldg(&g_badj[j0+1]);
#pragma unroll
            for (int r = 0; r < 2; r++) {
                const int ob = ((((b*COUT + j0)*T2 + t)*S2 + d)*S2 + (2*ry+r))*S2 + 4*tx;
                float4 olo, ohi;
                olo.x = fmaxf(lo32(acc[p][r][0]) + bj0, 0.0f);
                olo.y = fmaxf(lo32(acc[p][r][1]) + bj0, 0.0f);
                olo.z = fmaxf(lo32(acc[p][r][2]) + bj0, 0.0f);
                olo.w = fmaxf(lo32(acc[p][r][3]) + bj0, 0.0f);
                ohi.x = fmaxf(hi32(acc[p][r][0]) + bj1, 0.0f);
                ohi.y = fmaxf(hi32(acc[p][r][1]) + bj1, 0.0f);
                ohi.z = fmaxf(hi32(acc[p][r][2]) + bj1, 0.0f);
                ohi.w = fmaxf(hi32(acc[p][r][3]) + bj1, 0.0f);
                *(float4*)&out[ob] = olo;
                *(float4*)&out[ob + T2*S2*S2*S2] = ohi;
            }
        }
    }
}

// ---------------------------------------------------------------------------
extern "C" void kernel_launch(void* const* d_in, const int* in_sizes, int n_in,
                              void* d_out, int out_size) {
    const float* x     = (const float*)d_in[0];
    const float* W1    = (const float*)d_in[1];
    const float* b1    = (const float*)d_in[2];
    const float* gamma = (const float*)d_in[3];
    const float* beta  = (const float*)d_in[4];
    const float* W2    = (const float*)d_in[5];
    const float* b2    = (const float*)d_in[6];
    float* out = (float*)d_out;

    const int smem1 = (3456*2 + 648*2) * 8;    // 65664 B
    const int smem2 = (2376*2 + 1944*2) * 8;   // 69120 B
    cudaFuncSetAttribute(conv1_k, cudaFuncAttributeMaxDynamicSharedMemorySize, smem1);
    cudaFuncSetAttribute(conv2_k, cudaFuncAttributeMaxDynamicSharedMemorySize, smem2);

    zero_stats_k<<<1, 32>>>();
    conv1_k<<<dim3(S1, T1/2, Bn), 512, smem1>>>(x, W1, b1);
    badj_k<<<COUT, 32>>>(W2, b2, gamma, beta);
    prepW_k<<<CMID, 256>>>(W2);
    conv2_k<<<dim3(S2, T2, Bn), 320, smem2>>>(out);
}

// round 12
// speedup vs baseline: 1.0678x; 1.0678x over previous
#include <cuda_runtime.h>
#include <cstdint>

#define EPS 1e-3f
#define Bn   8
#define CIN  4
#define T0   20
#define S0   24
#define CMID 12
#define T1   18
#define S1   22
#define COUT 36
#define T2   16
#define S2   20
#define HP   24              // padded w-stride of g_h (16B-aligned rows)

#define H_TOTAL (Bn*CMID*T1*S1*S1*HP)

typedef unsigned long long u64;

__device__ float g_h[H_TOTAL];
__device__ float g_stats[24];
__device__ float g_badj[COUT];
__device__ u64   g_Wp[CMID * 18 * 9 * 12];   // pre-scaled packed W2 per ci

__device__ __forceinline__ void ffma2(u64& d, u64 a, u64 b, u64 c) {
    asm("fma.rn.f32x2 %0, %1, %2, %3;" : "=l"(d) : "l"(a), "l"(b), "l"(c));
}
__device__ __forceinline__ u64 pack2(float a, float b) {
    u64 r; asm("mov.b64 %0, {%1, %2};" : "=l"(r) : "f"(a), "f"(b)); return r;
}
__device__ __forceinline__ float lo32(u64 v){ return __uint_as_float((unsigned)v); }
__device__ __forceinline__ float hi32(u64 v){ return __uint_as_float((unsigned)(v>>32)); }

__device__ __forceinline__ void cpa16(uint32_t s, const void* g){
    asm volatile("cp.async.ca.shared.global [%0], [%1], 16;" :: "r"(s), "l"(g));
}
#define CP_COMMIT asm volatile("cp.async.commit_group;")
#define CP_WAIT0  asm volatile("cp.async.wait_group 0;" ::: "memory")

extern __shared__ char smemraw[];

// ---------------------------------------------------------------------------
__global__ void zero_stats_k() {
    if (threadIdx.x < 24) g_stats[threadIdx.x] = 0.0f;
}

// ---------------------------------------------------------------------------
// conv1 + ReLU + stats.  Block = (b, 2 t-planes, d) pair of 22x22 planes.
// 512 thr = 2 ch-groups (6ch = 3 pairs) x 2 t-planes x 128 lanes (121 act).
__global__ void __launch_bounds__(512, 1) conv1_k(const float* __restrict__ x,
                                                  const float* __restrict__ Wg1,
                                                  const float* __restrict__ b1) {
    float2* A0 = (float2*)smemraw;                 // 12 x 24 x 12 f2 = 3456
    float2* A1 = A0 + 3456;
    u64*    Wb0 = (u64*)(A1 + 3456);               // 6p x 9s x 12 = 648
    u64*    Wb1 = Wb0 + 648;
    __shared__ float sred[24];

    const int d  = blockIdx.x;
    const int t0 = 2 * blockIdx.y;
    const int b  = blockIdx.z;
    const int tid = threadIdx.x;
    const int cg  = tid >> 8;
    const int half = tid & 255;
    const int tp  = half >> 7;
    const int pid = half & 127;
    const bool act = pid < 121;
    const int ry = pid / 11;
    const int tx = pid - ry * 11;

    const uint32_t sA0 = (uint32_t)__cvta_generic_to_shared(A0);
    const uint32_t sA1 = (uint32_t)__cvta_generic_to_shared(A1);

    if (tid < 24) sred[tid] = 0.0f;

    auto stageA = [&](uint32_t sbuf, int ci){
#pragma unroll
        for (int k = 0; k < 4; k++) {
            const int i = tid + k * 512;
            if (i < 1728) {
                const int su = i / 144, rem = i - 144*su;
                const int rr = rem / 6, q = rem - 6*rr;
                const int kt4 = su / 3, kd = su - 3*kt4;
                const float* src = x + ((b*CIN + ci)*T0 + (t0+kt4))*(S0*S0*S0)
                                     + (d + kd)*(S0*S0) + rr*S0 + 4*q;
                cpa16(sbuf + (uint32_t)((su*288 + rr*12 + 2*q)*8), src);
            }
        }
    };
    auto stageW = [&](u64* wbuf, int ci){
        const int i = tid;
        if (i < 486) {
            const int p = i / 81, r = i - 81*p;
            const int s = r / 9, t9 = r - 9*s;
            const int kh = t9 / 3, kw = t9 - 3*kh;
            const float w0 = Wg1[(2*p*CIN + ci)*81 + r];
            const float w1 = Wg1[((2*p+1)*CIN + ci)*81 + r];
            wbuf[((p*9 + s)*3 + kh)*4 + kw] = pack2(w0, w1);
        }
    };

    stageA(sA0, 0); CP_COMMIT;
    stageW(Wb0, 0);
    CP_WAIT0;
    __syncthreads();

    u64 acc[3][2][2];
#pragma unroll
    for (int p = 0; p < 3; p++)
#pragma unroll
        for (int r = 0; r < 2; r++) { acc[p][r][0] = 0ull; acc[p][r][1] = 0ull; }

    for (int ci = 0; ci < CIN; ci++) {
        const float2* Ac = (ci & 1) ? A1 : A0;
        const u64*    Wc = (ci & 1) ? Wb1 : Wb0;
        if (ci < CIN-1) {
            stageA((ci & 1) ? sA0 : sA1, ci+1); CP_COMMIT;
            stageW((ci & 1) ? Wb0 : Wb1, ci+1);
        }
        if (act) {
            for (int s9 = 0; s9 < 9; s9++) {
                const int su = s9 + 3*tp;
                u64 xx[4][4];
#pragma unroll
                for (int kr = 0; kr < 4; kr++) {
                    const float2* rp = &Ac[su*288 + (2*ry + kr)*12 + tx];
                    const float2 f0 = rp[0], f1 = rp[1];
                    xx[kr][0] = pack2(f0.x, f0.x);
                    xx[kr][1] = pack2(f0.y, f0.y);
                    xx[kr][2] = pack2(f1.x, f1.x);
                    xx[kr][3] = pack2(f1.y, f1.y);
                }
#pragma unroll
                for (int kh = 0; kh < 3; kh++)
#pragma unroll
                    for (int p = 0; p < 3; p++) {
                        const u64* wb = Wc + ((cg*3 + p)*9 + s9)*12 + kh*4;
                        const ulonglong2 wab = *(const ulonglong2*)wb;
                        const u64 w2v = wb[2];
#pragma unroll
                        for (int r = 0; r < 2; r++)
#pragma unroll
                            for (int c = 0; c < 2; c++) {
                                ffma2(acc[p][r][c], wab.x, xx[r+kh][c+0], acc[p][r][c]);
                                ffma2(acc[p][r][c], wab.y, xx[r+kh][c+1], acc[p][r][c]);
                                ffma2(acc[p][r][c], w2v,   xx[r+kh][c+2], acc[p][r][c]);
                            }
                    }
            }
        }
        CP_WAIT0;
        __syncthreads();
    }

    float ss[3][2] = {{0,0},{0,0},{0,0}}, qq[3][2] = {{0,0},{0,0},{0,0}};
    const int t = t0 + tp;
    if (act) {
#pragma unroll
        for (int p = 0; p < 3; p++) {
            const int j0 = 2*(cg*3 + p);
            const float bj0 = __ldg(&b1[j0]), bj1 = __ldg(&b1[j0+1]);
#pragma unroll
            for (int r = 0; r < 2; r++) {
                const float v00 = fmaxf(lo32(acc[p][r][0]) + bj0, 0.0f);
                const float v01 = fmaxf(lo32(acc[p][r][1]) + bj0, 0.0f);
                const float v10 = fmaxf(hi32(acc[p][r][0]) + bj1, 0.0f);
                const float v11 = fmaxf(hi32(acc[p][r][1]) + bj1, 0.0f);
                const int hb = ((((b*CMID + j0)*T1 + t)*S1 + d)*S1 + (2*ry+r))*HP + 2*tx;
                *(float2*)&g_h[hb] = make_float2(v00, v01);
                *(float2*)&g_h[hb + T1*S1*S1*HP] = make_float2(v10, v11);
                ss[p][0] += v00 + v01;  qq[p][0] += v00*v00 + v01*v01;
                ss[p][1] += v10 + v11;  qq[p][1] += v10*v10 + v11*v11;
            }
        }
    }
    const int lane = tid & 31;
#pragma unroll
    for (int p = 0; p < 3; p++)
#pragma unroll
        for (int hlf = 0; hlf < 2; hlf++) {
            float s_ = ss[p][hlf], q_ = qq[p][hlf];
#pragma unroll
            for (int o = 16; o > 0; o >>= 1) {
                s_ += __shfl_down_sync(0xffffffffu, s_, o);
                q_ += __shfl_down_sync(0xffffffffu, q_, o);
            }
            if (lane == 0) {
                const int j = 2*(cg*3 + p) + hlf;
                atomicAdd(&sred[j], s_);
                atomicAdd(&sred[12 + j], q_);
            }
        }
    __syncthreads();
    if (tid < 24) atomicAdd(&g_stats[tid], sred[tid]);
}

// ---------------------------------------------------------------------------
// Merged finalize + bias-adjust + weight-prep.  48 blocks x 128 thr.
// Every block derives scale/shift locally from g_stats (no cross-block dep).
// Blocks 0..35: g_badj[j].  Blocks 36..47: pack g_Wp for ci = blk-36.
__global__ void prep_k(const float* __restrict__ W2,
                       const float* __restrict__ b2,
                       const float* __restrict__ gamma,
                       const float* __restrict__ beta) {
    const int blk = blockIdx.x;
    const int tid = threadIdx.x;
    __shared__ float ssh[CMID], ssc[CMID], red[4];
    if (tid < CMID) {
        const float N = (float)(Bn * T1 * S1 * S1 * S1);
        const float mean = g_stats[tid] / N;
        const float var  = g_stats[12 + tid] / N - mean * mean;
        const float inv  = rsqrtf(var + EPS);
        const float sc   = gamma[tid] * inv;
        ssc[tid] = sc;
        ssh[tid] = beta[tid] - mean * sc;
    }
    __syncthreads();

    if (blk < COUT) {
        const int j = blk;
        float sum = 0.0f;
        for (int e = tid; e < CMID*81; e += 128)
            sum += W2[j*CMID*81 + e] * ssh[e / 81];
#pragma unroll
        for (int o = 16; o > 0; o >>= 1)
            sum += __shfl_down_sync(0xffffffffu, sum, o);
        if ((tid & 31) == 0) red[tid >> 5] = sum;
        __syncthreads();
        if (tid == 0) g_badj[j] = b2[j] + red[0] + red[1] + red[2] + red[3];
    } else {
        const int ci = blk - COUT;
        const float sc = ssc[ci];
        for (int i = tid; i < 18*81; i += 128) {
            const int p = i / 81, r = i - 81*p;
            const int s = r / 9, t9 = r - 9*s;
            const int kh = t9 / 3, kw = t9 - 3*kh;
            const float w0 = W2[(2*p*CMID + ci)*81 + r] * sc;
            const float w1 = W2[((2*p+1)*CMID + ci)*81 + r] * sc;
            g_Wp[((ci*18 + p)*9 + s)*12 + kh*4 + kw] = pack2(w0, w1);
        }
    }
}

// ---------------------------------------------------------------------------
// conv2 + ReLU.  Block = (b,t,d) 20x20 plane, all 36 ch.  480 thr: 9
// ch-groups (4ch = 2 pairs) x 50 tiles (2r x 4c).  2-ci chunked cp.async
// double-buffered staging (6 barriers), pre-packed weights.
__global__ void __launch_bounds__(480, 1) conv2_k(float* __restrict__ out) {
    float2* A0 = (float2*)smemraw;                 // 2ci x 9su x 264 = 4752 f2
    float2* A1 = A0 + 4752;
    u64*    Wb0 = (u64*)(A1 + 4752);               // 2ci x 1944 = 3888 u64
    u64*    Wb1 = Wb0 + 3888;

    const int d = blockIdx.x, t = blockIdx.y, b = blockIdx.z;
    const int tid = threadIdx.x;
    const bool act = tid < 450;
    const int cg  = tid / 50;              // 0..8
    const int pid = tid - cg * 50;
    const int ry = pid / 5;                // rows 2ry,2ry+1
    const int tx = pid - ry * 5;           // cols 4tx..4tx+3

    const uint32_t sA0 = (uint32_t)__cvta_generic_to_shared(A0);
    const uint32_t sA1 = (uint32_t)__cvta_generic_to_shared(A1);
    const uint32_t sW0 = (uint32_t)__cvta_generic_to_shared(Wb0);
    const uint32_t sW1 = (uint32_t)__cvta_generic_to_shared(Wb1);

    auto stageA2 = [&](uint32_t sbuf, int ci0){
#pragma unroll
        for (int k = 0; k < 5; k++) {
            const int i = tid + k * 480;
            if (i < 2376) {
                const int cc = i / 1188, rem = i - 1188*cc;
                const int su = rem / 132, r2 = rem - 132*su;
                const int rr = r2 / 6, q = r2 - 6*rr;
                const int kt = su / 3, kd = su - 3*kt;
                const float* src = g_h + ((((b*CMID + ci0 + cc)*T1 + (t+kt))*S1
                                   + (d + kd))*S1 + rr)*HP + 4*q;
                cpa16(sbuf + (uint32_t)(((cc*9 + su)*264 + rr*12 + 2*q)*8), src);
            }
        }
    };
    auto stageW2 = [&](uint32_t sbuf, int ci0){
        const u64* src = g_Wp + ci0 * 1944;
#pragma unroll
        for (int k = 0; k < 5; k++) {
            const int i = tid + k * 480;
            if (i < 1944) cpa16(sbuf + (uint32_t)(i*16), src + 2*i);
        }
    };

    stageA2(sA0, 0);
    stageW2(sW0, 0);
    CP_COMMIT;
    CP_WAIT0;
    __syncthreads();

    u64 acc[2][2][4];
#pragma unroll
    for (int p = 0; p < 2; p++)
#pragma unroll
        for (int r = 0; r < 2; r++)
#pragma unroll
            for (int c = 0; c < 4; c++) acc[p][r][c] = 0ull;

    for (int ch = 0; ch < 6; ch++) {
        const float2* Ac = (ch & 1) ? A1 : A0;
        const u64*    Wc = (ch & 1) ? Wb1 : Wb0;
        if (ch < 5) {
            stageA2((ch & 1) ? sA0 : sA1, 2*ch + 2);
            stageW2((ch & 1) ? sW0 : sW1, 2*ch + 2);
            CP_COMMIT;
        }
        if (act) {
#pragma unroll
            for (int cil = 0; cil < 2; cil++) {
                for (int s9 = 0; s9 < 9; s9++) {
                    u64 xx[4][6];
#pragma unroll
                    for (int kr = 0; kr < 4; kr++) {
                        const float* rp = (const float*)
                            &Ac[(cil*9 + s9)*264 + (2*ry + kr)*12 + 2*tx];
                        const float4 v4 = *(const float4*)rp;
                        const float2 v2 = *(const float2*)(rp + 4);
                        xx[kr][0] = pack2(v4.x, v4.x);
                        xx[kr][1] = pack2(v4.y, v4.y);
                        xx[kr][2] = pack2(v4.z, v4.z);
                        xx[kr][3] = pack2(v4.w, v4.w);
                        xx[kr][4] = pack2(v2.x, v2.x);
                        xx[kr][5] = pack2(v2.y, v2.y);
                    }
#pragma unroll
                    for (int kh = 0; kh < 3; kh++)
#pragma unroll
                        for (int p = 0; p < 2; p++) {
                            const u64* wb = Wc + cil*1944
                                          + (cg*2 + p)*108 + s9*12 + kh*4;
                            const ulonglong2 wab = *(const ulonglong2*)wb;
                            const u64 w2v = wb[2];
#pragma unroll
                            for (int r = 0; r < 2; r++)
#pragma unroll
                                for (int c = 0; c < 4; c++) {
                                    ffma2(acc[p][r][c], wab.x, xx[r+kh][c+0], acc[p][r][c]);
                                    ffma2(acc[p][r][c], wab.y, xx[r+kh][c+1], acc[p][r][c]);
                                    ffma2(acc[p][r][c], w2v,   xx[r+kh][c+2], acc[p][r][c]);
                                }
                        }
                }
            }
        }
        CP_WAIT0;
        __syncthreads();
    }

    if (act) {
#pragma unroll
        for (int p = 0; p < 2; p++) {
            const int j0 = 4*cg + 2*p;
            const float bj0 = __ldg(&g_badj[j0]), bj1 = __ldg(&g_badj[j0+1]);
#pragma unroll
            for (int r = 0; r < 2; r++) {
                const int ob = ((((b*COUT + j0)*T2 + t)*S2 + d)*S2 + (2*ry+r))*S2 + 4*tx;
                float4 olo, ohi;
                olo.x = fmaxf(lo32(acc[p][r][0]) + bj0, 0.0f);
                olo.y = fmaxf(lo32(acc[p][r][1]) + bj0, 0.0f);
                olo.z = fmaxf(lo32(acc[p][r][2]) + bj0, 0.0f);
                olo.w = fmaxf(lo32(acc[p][r][3]) + bj0, 0.0f);
                ohi.x = fmaxf(hi32(acc[p][r][0]) + bj1, 0.0f);
                ohi.y = fmaxf(hi32(acc[p][r][1]) + bj1, 0.0f);
                ohi.z = fmaxf(hi32(acc[p][r][2]) + bj1, 0.0f);
                ohi.w = fmaxf(hi32(acc[p][r][3]) + bj1, 0.0f);
                *(float4*)&out[ob] = olo;
                *(float4*)&out[ob + T2*S2*S2*S2] = ohi;
            }
        }
    }
}

// ---------------------------------------------------------------------------
extern "C" void kernel_launch(void* const* d_in, const int* in_sizes, int n_in,
                              void* d_out, int out_size) {
    const float* x     = (const float*)d_in[0];
    const float* W1    = (const float*)d_in[1];
    const float* b1    = (const float*)d_in[2];
    const float* gamma = (const float*)d_in[3];
    const float* beta  = (const float*)d_in[4];
    const float* W2    = (const float*)d_in[5];
    const float* b2    = (const float*)d_in[6];
    float* out = (float*)d_out;

    const int smem1 = (3456*2 + 648*2) * 8;      // 65664 B
    const int smem2 = (4752*2 + 3888*2) * 8;     // 138240 B
    cudaFuncSetAttribute(conv1_k, cudaFuncAttributeMaxDynamicSharedMemorySize, smem1);
    cudaFuncSetAttribute(conv2_k, cudaFuncAttributeMaxDynamicSharedMemorySize, smem2);

    zero_stats_k<<<1, 32>>>();
    conv1_k<<<dim3(S1, T1/2, Bn), 512, smem1>>>(x, W1, b1);
    prep_k<<<COUT + CMID, 128>>>(W2, b2, gamma, beta);
    conv2_k<<<dim3(S2, T2, Bn), 480, smem2>>>(out);
}